// round 1
// baseline (speedup 1.0000x reference)
#include <cuda_runtime.h>
#include <stdint.h>

#define FULLMASK 0xffffffffu

// ---------------- scratch (device globals; no allocation allowed) ----------------
__device__ __align__(16) uint32_t g_A2[128*32*32*4];   // packed acts into layer2 (32x32, 128ch)
__device__ __align__(16) uint32_t g_A3[128*16*16*4];   // into layer3 (16x16, 128ch)
__device__ __align__(16) uint32_t g_A4[128*16*16*8];   // into layer4 (16x16, 256ch)
__device__ __align__(16) uint32_t g_A5[128*8*8*8];     // into layer5 (8x8, 256ch)
__device__ __align__(16) uint32_t g_A6[128*8*8*16];    // into layer6 (8x8, 512ch)
__device__ __align__(16) float    g_H6[128*4*4*512];   // float acts after layer6 pool+bn
__device__ __align__(16) uint32_t g_W2[9*4*128];
__device__ __align__(16) uint32_t g_W3[9*4*256];
__device__ __align__(16) uint32_t g_W4[9*8*256];
__device__ __align__(16) uint32_t g_W5[9*8*512];
__device__ __align__(16) uint32_t g_W6[9*16*512];

// ---------------- weight sign-packing ----------------
// layout: wp[(tap*words + wd)*Cout + cout], bit b of word wd <-> cin = wd*32+b, bit=1 <=> w>0
__global__ void pack_w_kernel(const float* __restrict__ w, int words, int Cout, int layer) {
    int idx = blockIdx.x * blockDim.x + threadIdx.x;
    int total = 9 * words * Cout;
    if (idx >= total) return;
    uint32_t* wp = (layer == 2) ? g_W2 : (layer == 3) ? g_W3 :
                   (layer == 4) ? g_W4 : (layer == 5) ? g_W5 : g_W6;
    int cout = idx % Cout;
    int t2   = idx / Cout;
    int wd   = t2 % words;
    int tap  = t2 / words;
    int Cin  = words * 32;
    const float* base = w + ((size_t)tap * Cin + (size_t)wd * 32) * Cout + cout;
    uint32_t bits = 0;
    for (int bb = 0; bb < 32; ++bb)
        if (base[(size_t)bb * Cout] > 0.f) bits |= (1u << bb);
    wp[idx] = bits;
}

// ---------------- layer 1: float conv 3->128 + relu + b1 + bn1 + binarize-pack ----------------
// grid(32 rows, 128 batch), block 128 threads (one per cout)
__global__ __launch_bounds__(128) void conv1_kernel(
    const float* __restrict__ x, const float* __restrict__ w1,
    const float* __restrict__ b1, const float* __restrict__ sc1,
    const float* __restrict__ bi1)
{
    __shared__ float xs[3 * 34 * 3];   // 3 rows, cols -1..32 zero-padded, 3 ch
    const int tid = threadIdx.x;
    const int y = blockIdx.x, b = blockIdx.y;

    for (int i = tid; i < 3 * 34 * 3; i += 128) xs[i] = 0.f;
    __syncthreads();
    for (int j = 0; j < 3; ++j) {
        int gy = y + j - 1;
        if (gy < 0 || gy >= 32) continue;
        if (tid < 96) {
            int c = tid / 3, ci = tid % 3;
            xs[(j * 34 + c + 1) * 3 + ci] = x[((size_t)(b * 32 + gy) * 32 + c) * 3 + ci];
        }
    }
    __syncthreads();

    float wr[27];
    #pragma unroll
    for (int k = 0; k < 27; ++k) wr[k] = w1[k * 128 + tid];
    const float bv = b1[tid], scv = sc1[tid], biv = bi1[tid];
    const int lane = tid & 31, warp = tid >> 5;

    for (int c = 0; c < 32; ++c) {
        float sum = 0.f;
        #pragma unroll
        for (int ky = 0; ky < 3; ++ky)
            #pragma unroll
            for (int kx = 0; kx < 3; ++kx)
                #pragma unroll
                for (int ci = 0; ci < 3; ++ci)
                    sum += xs[(ky * 34 + c + kx) * 3 + ci] * wr[(ky * 3 + kx) * 3 + ci];
        float h = fmaxf(sum + bv, 0.f);
        float f = __fadd_rn(__fmul_rn(h, scv), biv);
        unsigned bits = __ballot_sync(FULLMASK, f > 0.f);
        if (lane == 0) g_A2[((size_t)(b * 32 + y) * 32 + c) * 4 + warp] = bits;
    }
}

// ---------------- generic binary conv (XNOR-popcount) ----------------
// block: 128 threads = 128 consecutive output channels
// grid: (H/2 row-tiles, COUT/128 chunks, 128 batch)
template <int H, int W, int NW, int CIN, int COUT, bool POOL, bool FOUT>
__device__ __forceinline__ void binconv_body(
    const uint32_t* __restrict__ A, const uint32_t* __restrict__ Wp,
    const float* __restrict__ scale, const float* __restrict__ bias,
    uint32_t* __restrict__ Aout, float* __restrict__ Fout)
{
    constexpr int RW = W * NW;
    __shared__ __align__(16) uint32_t s[4 * RW];
    const int tid = threadIdx.x;
    const int t   = blockIdx.x;
    const int b   = blockIdx.z;
    const int cout = blockIdx.y * 128 + tid;
    const int y0  = 2 * t;

    // stage rows [y0-1, y0+2] of the packed input image
    for (int idx = tid; idx < 4 * RW; idx += 128) {
        int j = idx / RW;
        int gy = y0 - 1 + j;
        if (gy >= 0 && gy < H)
            s[idx] = A[((size_t)(b * H + gy) * W) * NW + (idx - j * RW)];
    }
    __syncthreads();

    int acc[2 * W];
    #pragma unroll
    for (int i = 0; i < 2 * W; ++i) acc[i] = 0;

    for (int ky = 0; ky < 3; ++ky) {
        for (int kx = 0; kx < 3; ++kx) {
            uint32_t wr[NW];
            const uint32_t* wp = Wp + (size_t)((ky * 3 + kx) * NW) * COUT + cout;
            #pragma unroll
            for (int i = 0; i < NW; ++i) wr[i] = wp[(size_t)i * COUT];
            const int dx = kx - 1;
            #pragma unroll
            for (int r = 0; r < 2; ++r) {
                int gy = y0 + r + ky - 1;
                if (gy < 0 || gy >= H) continue;
                const uint32_t* arow = s + (r + ky) * RW;
                #pragma unroll
                for (int c = 0; c < W; ++c) {
                    int sx = c + dx;
                    if (sx >= 0 && sx < W) {
                        const uint32_t* ap = arow + sx * NW;
                        int ps = 0;
                        #pragma unroll
                        for (int i = 0; i < NW; i += 4) {
                            uint4 av = *reinterpret_cast<const uint4*>(ap + i);
                            ps += __popc(av.x ^ wr[i])     + __popc(av.y ^ wr[i + 1])
                                + __popc(av.z ^ wr[i + 2]) + __popc(av.w ^ wr[i + 3]);
                        }
                        acc[r * W + c] += ps;
                    }
                }
            }
        }
    }

    const float scv = scale[cout];
    const float biv = bias[cout];
    const int lane = tid & 31;
    const int widx = blockIdx.y * 4 + (tid >> 5);
    constexpr int NWOUT = COUT / 32;

    auto cval = [&](int r, int c) {
        int gy = y0 + r;
        int nv = (3 - (gy == 0) - (gy == H - 1)) * (3 - (c == 0) - (c == W - 1));
        int v = CIN * nv - 2 * acc[r * W + c];   // exact conv sum over valid taps
        return v > 0 ? v : 0;                    // relu
    };

    if constexpr (POOL) {
        #pragma unroll
        for (int oc = 0; oc < W / 2; ++oc) {
            int m = max(max(cval(0, 2 * oc), cval(0, 2 * oc + 1)),
                        max(cval(1, 2 * oc), cval(1, 2 * oc + 1)));
            float f = __fadd_rn(__fmul_rn((float)m, scv), biv);
            if constexpr (FOUT) {
                Fout[((size_t)(b * (H / 2) + t) * (W / 2) + oc) * COUT + cout] = f;
            } else {
                unsigned bits = __ballot_sync(FULLMASK, f > 0.f);
                if (lane == 0)
                    Aout[((size_t)(b * (H / 2) + t) * (W / 2) + oc) * NWOUT + widx] = bits;
            }
        }
    } else {
        #pragma unroll
        for (int r = 0; r < 2; ++r) {
            int gy = y0 + r;
            #pragma unroll
            for (int c = 0; c < W; ++c) {
                int v = cval(r, c);
                float f = __fadd_rn(__fmul_rn((float)v, scv), biv);
                unsigned bits = __ballot_sync(FULLMASK, f > 0.f);
                if (lane == 0)
                    Aout[((size_t)(b * H + gy) * W + c) * NWOUT + widx] = bits;
            }
        }
    }
}

__global__ __launch_bounds__(128) void l2_kernel(const float* sc, const float* bi) {
    binconv_body<32, 32, 4, 128, 128, true,  false>(g_A2, g_W2, sc, bi, g_A3, nullptr);
}
__global__ __launch_bounds__(128) void l3_kernel(const float* sc, const float* bi) {
    binconv_body<16, 16, 4, 128, 256, false, false>(g_A3, g_W3, sc, bi, g_A4, nullptr);
}
__global__ __launch_bounds__(128) void l4_kernel(const float* sc, const float* bi) {
    binconv_body<16, 16, 8, 256, 256, true,  false>(g_A4, g_W4, sc, bi, g_A5, nullptr);
}
__global__ __launch_bounds__(128) void l5_kernel(const float* sc, const float* bi) {
    binconv_body<8, 8, 8, 256, 512, false, false>(g_A5, g_W5, sc, bi, g_A6, nullptr);
}
__global__ __launch_bounds__(128) void l6_kernel(const float* sc, const float* bi) {
    binconv_body<8, 8, 16, 512, 512, true, true>(g_A6, g_W6, sc, bi, nullptr, g_H6);
}

// ---------------- dense (512->10) + softmax, one warp per pixel ----------------
__global__ __launch_bounds__(128) void dense_kernel(
    const float* __restrict__ dw, const float* __restrict__ db, float* __restrict__ out)
{
    __shared__ float sdw[512 * 10];   // transposed: sdw[d*512 + c]
    const int tid = threadIdx.x;
    for (int i = tid; i < 5120; i += 128) {
        int c = i / 10, d = i % 10;
        sdw[d * 512 + c] = dw[i];
    }
    __syncthreads();
    const int warp = tid >> 5, lane = tid & 31;
    const int p = blockIdx.x * 4 + warp;   // pixel in [0, 2048)
    float lg[10];
    #pragma unroll
    for (int d = 0; d < 10; ++d) lg[d] = 0.f;
    for (int c = lane; c < 512; c += 32) {
        float h = g_H6[(size_t)p * 512 + c];
        #pragma unroll
        for (int d = 0; d < 10; ++d) lg[d] += h * sdw[d * 512 + c];
    }
    #pragma unroll
    for (int d = 0; d < 10; ++d)
        for (int off = 16; off; off >>= 1)
            lg[d] += __shfl_xor_sync(FULLMASK, lg[d], off);
    if (lane == 0) {
        float l[10], mx = -1e30f;
        #pragma unroll
        for (int d = 0; d < 10; ++d) { l[d] = lg[d] + db[d]; mx = fmaxf(mx, l[d]); }
        float e[10], ssum = 0.f;
        #pragma unroll
        for (int d = 0; d < 10; ++d) { e[d] = expf(l[d] - mx); ssum += e[d]; }
        float inv = 1.f / ssum;
        #pragma unroll
        for (int d = 0; d < 10; ++d) out[(size_t)p * 10 + d] = e[d] * inv;
    }
}

// ---------------- launch ----------------
extern "C" void kernel_launch(void* const* d_in, const int* in_sizes, int n_in,
                              void* d_out, int out_size)
{
    const float* P[22];
    for (int i = 0; i < 22 && i < n_in; ++i) P[i] = (const float*)d_in[i];

    const float *x, *w1, *b1, *w2, *w3, *w4, *w5, *w6;
    const float *bn1s, *bn1b, *bn2s, *bn2b, *bn3s, *bn3b, *bn4s, *bn4b, *bn5s, *bn5b, *bn6s, *bn6b;
    const float *dw, *db;

    if (in_sizes[3] == 147456) {
        // setup_inputs dict order: x,w1,b1,w2..w6,bn1s,bn1b,...,bn6s,bn6b,dense_w,dense_b
        x = P[0];  w1 = P[1]; b1 = P[2];
        w2 = P[3]; w3 = P[4]; w4 = P[5]; w5 = P[6]; w6 = P[7];
        bn1s = P[8];  bn1b = P[9];  bn2s = P[10]; bn2b = P[11];
        bn3s = P[12]; bn3b = P[13]; bn4s = P[14]; bn4b = P[15];
        bn5s = P[16]; bn5b = P[17]; bn6s = P[18]; bn6b = P[19];
        dw = P[20]; db = P[21];
    } else {
        // reference() signature order
        x = P[0];  w1 = P[1]; b1 = P[2]; bn1s = P[3]; bn1b = P[4];
        w2 = P[5];  bn2s = P[6];  bn2b = P[7];
        w3 = P[8];  bn3s = P[9];  bn3b = P[10];
        w4 = P[11]; bn4s = P[12]; bn4b = P[13];
        w5 = P[14]; bn5s = P[15]; bn5b = P[16];
        w6 = P[17]; bn6s = P[18]; bn6b = P[19];
        dw = P[20]; db = P[21];
    }

    // weight sign-packing
    pack_w_kernel<<<(9 * 4 * 128 + 255) / 256, 256>>>(w2, 4, 128, 2);
    pack_w_kernel<<<(9 * 4 * 256 + 255) / 256, 256>>>(w3, 4, 256, 3);
    pack_w_kernel<<<(9 * 8 * 256 + 255) / 256, 256>>>(w4, 8, 256, 4);
    pack_w_kernel<<<(9 * 8 * 512 + 255) / 256, 256>>>(w5, 8, 512, 5);
    pack_w_kernel<<<(9 * 16 * 512 + 255) / 256, 256>>>(w6, 16, 512, 6);

    // layer 1 (float conv) -> packed bits
    conv1_kernel<<<dim3(32, 128), 128>>>(x, w1, b1, bn1s, bn1b);

    // binary layers
    l2_kernel<<<dim3(16, 1, 128), 128>>>(bn2s, bn2b);
    l3_kernel<<<dim3(8, 2, 128), 128>>>(bn3s, bn3b);
    l4_kernel<<<dim3(8, 2, 128), 128>>>(bn4s, bn4b);
    l5_kernel<<<dim3(4, 4, 128), 128>>>(bn5s, bn5b);
    l6_kernel<<<dim3(4, 4, 128), 128>>>(bn6s, bn6b);

    // dense + softmax
    dense_kernel<<<512, 128>>>(dw, db, (float*)d_out);
}